// round 1
// baseline (speedup 1.0000x reference)
#include <cuda_runtime.h>
#include <math.h>

typedef unsigned long long ull;

#define NB   64        // batch
#define NTT  512       // timesteps
#define NE   1024      // encoder hidden
#define ND   1024      // decoder hidden
#define NF   2048      // 2E
#define NM   (NTT*NB)  // 32768 rows of the big GEMM
#define NTILES 16      // 2048 / 128 N-tiles

// ---------------- scratch (__device__ globals; no allocations) ----------------
__device__ float g_hproj[NB * NF];          // [64, 2048]
__device__ float g_spart[NM * NTILES];      // partial scores per N-tile
__device__ float g_weights[NB * NTT];       // softmax weights [64, 512]

// ---------------- f32x2 helpers ----------------
__device__ __forceinline__ ull pk2(float lo, float hi) {
    ull r; asm("mov.b64 %0, {%1, %2};" : "=l"(r) : "f"(lo), "f"(hi)); return r;
}
__device__ __forceinline__ void upk2(ull v, float &lo, float &hi) {
    asm("mov.b64 {%0, %1}, %2;" : "=f"(lo), "=f"(hi) : "l"(v));
}
__device__ __forceinline__ void ffma2(ull &d, ull a, ull b) {
    asm("fma.rn.f32x2 %0, %1, %2, %0;" : "+l"(d) : "l"(a), "l"(b));
}

// =====================================================================
// K2: fused  spart[m, nt] = sum_{f in tile nt} w2[f] * tanh( h_proj[m%64, f]
//                + sum_k enc[m, k] * Wa[f, 1024+k] )
// Tile: BM=128, BN=128, BK=16, 256 threads, 8x8 per thread via f32x2.
// grid: (x = n-tile [16], y = m-tile [256])
// =====================================================================
__global__ __launch_bounds__(256, 2)
void fused_scores_kernel(const float* __restrict__ enc,
                         const float* __restrict__ Wa,
                         const float* __restrict__ w2)
{
    __shared__ __align__(16) float As[2][16][128];
    __shared__ __align__(16) float Bs[2][16][128];

    const int tid = threadIdx.x;
    const int tx  = tid & 15;       // col group (8 cols)
    const int ty  = tid >> 4;       // row group (8 rows)
    const int n0  = blockIdx.x * 128;
    const int m0  = blockIdx.y * 128;

    const int rowA  = tid >> 1;         // 0..127
    const int halfk = (tid & 1) * 8;    // 0 or 8

    const float* gA = enc + (size_t)(m0 + rowA) * 1024 + halfk;
    const float* gB = Wa  + (size_t)(n0 + rowA) * 2048 + 1024 + halfk;

    ull acc[8][4];
#pragma unroll
    for (int i = 0; i < 8; i++)
#pragma unroll
        for (int j = 0; j < 4; j++) acc[i][j] = 0ull;

    // prologue: chunk 0
    float4 ra0 = *(const float4*)(gA);
    float4 ra1 = *(const float4*)(gA + 4);
    float4 rb0 = *(const float4*)(gB);
    float4 rb1 = *(const float4*)(gB + 4);

    As[0][halfk+0][rowA]=ra0.x; As[0][halfk+1][rowA]=ra0.y;
    As[0][halfk+2][rowA]=ra0.z; As[0][halfk+3][rowA]=ra0.w;
    As[0][halfk+4][rowA]=ra1.x; As[0][halfk+5][rowA]=ra1.y;
    As[0][halfk+6][rowA]=ra1.z; As[0][halfk+7][rowA]=ra1.w;
    Bs[0][halfk+0][rowA]=rb0.x; Bs[0][halfk+1][rowA]=rb0.y;
    Bs[0][halfk+2][rowA]=rb0.z; Bs[0][halfk+3][rowA]=rb0.w;
    Bs[0][halfk+4][rowA]=rb1.x; Bs[0][halfk+5][rowA]=rb1.y;
    Bs[0][halfk+6][rowA]=rb1.z; Bs[0][halfk+7][rowA]=rb1.w;
    __syncthreads();

    int buf = 0;
#pragma unroll 1
    for (int ch = 0; ch < 64; ch++) {
        if (ch < 63) {
            const float* pA = gA + (ch + 1) * 16;
            const float* pB = gB + (ch + 1) * 16;
            ra0 = *(const float4*)(pA);
            ra1 = *(const float4*)(pA + 4);
            rb0 = *(const float4*)(pB);
            rb1 = *(const float4*)(pB + 4);
        }
#pragma unroll
        for (int k = 0; k < 16; k++) {
            const float4 a0 = *(const float4*)&As[buf][k][ty*8];
            const float4 a1 = *(const float4*)&As[buf][k][ty*8+4];
            const ulonglong2 bq0 = *(const ulonglong2*)&Bs[buf][k][tx*8];
            const ulonglong2 bq1 = *(const ulonglong2*)&Bs[buf][k][tx*8+4];
            float av[8] = {a0.x,a0.y,a0.z,a0.w,a1.x,a1.y,a1.z,a1.w};
            ull bp[4] = {bq0.x, bq0.y, bq1.x, bq1.y};
#pragma unroll
            for (int i = 0; i < 8; i++) {
                ull ap = pk2(av[i], av[i]);
#pragma unroll
                for (int j = 0; j < 4; j++) ffma2(acc[i][j], ap, bp[j]);
            }
        }
        if (ch < 63) {
            const int nb = buf ^ 1;
            As[nb][halfk+0][rowA]=ra0.x; As[nb][halfk+1][rowA]=ra0.y;
            As[nb][halfk+2][rowA]=ra0.z; As[nb][halfk+3][rowA]=ra0.w;
            As[nb][halfk+4][rowA]=ra1.x; As[nb][halfk+5][rowA]=ra1.y;
            As[nb][halfk+6][rowA]=ra1.z; As[nb][halfk+7][rowA]=ra1.w;
            Bs[nb][halfk+0][rowA]=rb0.x; Bs[nb][halfk+1][rowA]=rb0.y;
            Bs[nb][halfk+2][rowA]=rb0.z; Bs[nb][halfk+3][rowA]=rb0.w;
            Bs[nb][halfk+4][rowA]=rb1.x; Bs[nb][halfk+5][rowA]=rb1.y;
            Bs[nb][halfk+6][rowA]=rb1.z; Bs[nb][halfk+7][rowA]=rb1.w;
            __syncthreads();
            buf = nb;
        }
    }

    // epilogue: tanh(acc + h_proj) * w2, reduce 8 cols per thread,
    // then across the 16 tx lanes (half-warp), write one partial per row.
    const float* w2p = w2 + n0 + tx * 8;
#pragma unroll
    for (int i = 0; i < 8; i++) {
        const int m = m0 + ty * 8 + i;
        const float* hp = g_hproj + (size_t)(m & 63) * 2048 + n0 + tx * 8;
        float s = 0.f;
#pragma unroll
        for (int j2 = 0; j2 < 4; j2++) {
            float lo, hi;
            upk2(acc[i][j2], lo, hi);
            s = fmaf(tanhf(lo + hp[2*j2]),   w2p[2*j2],   s);
            s = fmaf(tanhf(hi + hp[2*j2+1]), w2p[2*j2+1], s);
        }
        s += __shfl_down_sync(0xffffffffu, s, 8, 16);
        s += __shfl_down_sync(0xffffffffu, s, 4, 16);
        s += __shfl_down_sync(0xffffffffu, s, 2, 16);
        s += __shfl_down_sync(0xffffffffu, s, 1, 16);
        if (tx == 0) g_spart[(size_t)m * NTILES + blockIdx.x] = s;
    }
}

// =====================================================================
// Small generic GEMM: C = epi( [A|A2] @ B[:, bcol0:]^T + bias )
// 32x32 tile, 256 threads, 2x2 per thread. Cout==nullptr -> write g_hproj.
// =====================================================================
__global__ void small_gemm_kernel(const float* __restrict__ A,
                                  const float* __restrict__ A2, int ksplit, int lda,
                                  const float* __restrict__ Bm, int ldb, int bcol0,
                                  const float* __restrict__ bias,
                                  float* __restrict__ Cout, int ldc,
                                  int M, int N, int K, int do_tanh)
{
    __shared__ float As[16][33];
    __shared__ float Bs[16][33];
    float* C = Cout ? Cout : g_hproj;
    const int tid = threadIdx.x;
    const int tx = tid & 15, ty = tid >> 4;
    const int m0 = blockIdx.y * 32, n0 = blockIdx.x * 32;
    float acc00 = 0.f, acc01 = 0.f, acc10 = 0.f, acc11 = 0.f;

    for (int k0 = 0; k0 < K; k0 += 16) {
        for (int i = tid; i < 32 * 16; i += 256) {
            const int r = i >> 4, c = i & 15;
            const int m = m0 + r, k = k0 + c;
            float av = 0.f;
            if (m < M) av = (k < ksplit) ? A[(size_t)m*lda + k]
                                         : A2[(size_t)m*lda + (k - ksplit)];
            As[c][r] = av;
            const int n = n0 + r;
            Bs[c][r] = (n < N) ? Bm[(size_t)n*ldb + bcol0 + k] : 0.f;
        }
        __syncthreads();
#pragma unroll
        for (int k = 0; k < 16; k++) {
            const float a0 = As[k][ty*2], a1 = As[k][ty*2+1];
            const float b0 = Bs[k][tx*2], b1 = Bs[k][tx*2+1];
            acc00 = fmaf(a0, b0, acc00); acc01 = fmaf(a0, b1, acc01);
            acc10 = fmaf(a1, b0, acc10); acc11 = fmaf(a1, b1, acc11);
        }
        __syncthreads();
    }
    const float r2[2][2] = {{acc00, acc01}, {acc10, acc11}};
#pragma unroll
    for (int i = 0; i < 2; i++)
#pragma unroll
        for (int j = 0; j < 2; j++) {
            const int mm = m0 + ty*2 + i, nn = n0 + tx*2 + j;
            if (mm < M && nn < N) {
                float v = r2[i][j] + bias[nn];
                if (do_tanh) v = tanhf(v);
                C[(size_t)mm*ldc + nn] = v;
            }
        }
}

// =====================================================================
// K3+K4: scores[b,t] = sum_nt spart + b2; softmax over t -> g_weights
// one block per b, 256 threads, 2 t each
// =====================================================================
__global__ void softmax_kernel(const float* __restrict__ b2)
{
    const int b = blockIdx.x;
    const int tid = threadIdx.x;
    __shared__ float red[256];
    const float b2v = b2[0];

    float loc[2];
#pragma unroll
    for (int s = 0; s < 2; s++) {
        const int t = tid + s * 256;
        const float* p = g_spart + (size_t)(t * NB + b) * NTILES;
        float a = b2v;
#pragma unroll
        for (int n = 0; n < NTILES; n++) a += p[n];
        loc[s] = a;
    }
    // max
    red[tid] = fmaxf(loc[0], loc[1]);
    __syncthreads();
    for (int off = 128; off > 0; off >>= 1) {
        if (tid < off) red[tid] = fmaxf(red[tid], red[tid + off]);
        __syncthreads();
    }
    const float mx = red[0];
    __syncthreads();
    const float e0 = expf(loc[0] - mx);
    const float e1 = expf(loc[1] - mx);
    red[tid] = e0 + e1;
    __syncthreads();
    for (int off = 128; off > 0; off >>= 1) {
        if (tid < off) red[tid] += red[tid + off];
        __syncthreads();
    }
    const float inv = 1.f / red[0];
    g_weights[b * NTT + tid]       = e0 * inv;
    g_weights[b * NTT + tid + 256] = e1 * inv;
}

// =====================================================================
// K5: applied[b,e] = sum_t weights[b,t] * enc[t,b,e]   (writes d_out 2nd half)
// grid (E/256, B)
// =====================================================================
__global__ void applied_kernel(const float* __restrict__ enc,
                               float* __restrict__ applied)
{
    const int b = blockIdx.y;
    const int e = blockIdx.x * 256 + threadIdx.x;
    __shared__ float w[NTT];
    for (int i = threadIdx.x; i < NTT; i += 256) w[i] = g_weights[b * NTT + i];
    __syncthreads();
    const float* p = enc + (size_t)b * 1024 + e;
    float acc = 0.f;
#pragma unroll 8
    for (int t = 0; t < NTT; t++)
        acc = fmaf(w[t], p[(size_t)t * (NB * NE)], acc);
    applied[(size_t)b * NE + e] = acc;
}

// =====================================================================
extern "C" void kernel_launch(void* const* d_in, const int* in_sizes, int n_in,
                              void* d_out, int out_size)
{
    const float* hidden = (const float*)d_in[0];
    const float* dec    = (const float*)d_in[1];
    const float* enc    = (const float*)d_in[2];
    const float* Wa     = (const float*)d_in[3];
    const float* ba     = (const float*)d_in[4];
    const float* w2     = (const float*)d_in[5];
    const float* b2     = (const float*)d_in[6];
    const float* Wc     = (const float*)d_in[7];
    const float* bc     = (const float*)d_in[8];

    float* out     = (float*)d_out;            // [64,1024]
    float* applied = out + NB * ND;            // [64,1024]

    // K1: h_proj = hidden @ Wa[:, :1024]^T + ba  -> g_hproj (Cout=nullptr)
    small_gemm_kernel<<<dim3(NF/32, NB/32), 256>>>(
        hidden, hidden, /*ksplit=*/1024, /*lda=*/1024,
        Wa, /*ldb=*/2048, /*bcol0=*/0, ba,
        nullptr, /*ldc=*/NF, NB, NF, 1024, /*tanh=*/0);

    // K2: big fused GEMM + tanh + w2-dot -> g_spart
    fused_scores_kernel<<<dim3(NTILES, NM/128), 256>>>(enc, Wa, w2);

    // K3+K4: reduce partials + softmax -> g_weights
    softmax_kernel<<<NB, 256>>>(b2);

    // K5: applied = weights @ enc  -> d_out second half
    applied_kernel<<<dim3(NE/256, NB), 256>>>(enc, applied);

    // K6: out = tanh([dec|applied] @ Wc^T + bc) -> d_out first half
    small_gemm_kernel<<<dim3(ND/32, NB/32), 256>>>(
        dec, applied, /*ksplit=*/1024, /*lda=*/1024,
        Wc, /*ldb=*/2048, /*bcol0=*/0, bc,
        out, /*ldc=*/ND, NB, ND, 2048, /*tanh=*/1);
}

// round 3
// speedup vs baseline: 1.4320x; 1.4320x over previous
#include <cuda_runtime.h>
#include <cstdint>
#include <math.h>

#define NB   64
#define NTT  512
#define NE   1024
#define ND   1024
#define NF   2048
#define NM   (NTT*NB)
#define NTILES 8          // 2048 / 256 N-tiles

// ---------------- scratch ----------------
__device__ float g_hproj[NB * NF];
__device__ float g_spart[NM * NTILES];
__device__ float g_weights[NB * NTT];
__device__ float g_apart[4][NB * NE];

// ---------------- helpers ----------------
__device__ __forceinline__ float tf32r(float x) {
    // round-to-nearest tf32 on the ALU pipe
    unsigned u = __float_as_uint(x);
    u = (u + 0x1000u) & 0xFFFFE000u;
    return __uint_as_float(u);
}
__device__ __forceinline__ float fast_tanh(float x) {
    float cx = fminf(fmaxf(x, -30.f), 30.f);
    float e;
    asm("ex2.approx.f32 %0, %1;" : "=f"(e) : "f"(cx * 2.885390081777927f)); // e^(2x)
    float r;
    asm("rcp.approx.f32 %0, %1;" : "=f"(r) : "f"(e + 1.f));
    return (e - 1.f) * r;
}
__device__ __forceinline__ void mma_tf32(float* c, const uint4& a, unsigned b0, unsigned b1) {
    asm volatile(
        "mma.sync.aligned.m16n8k8.row.col.f32.tf32.tf32.f32 "
        "{%0,%1,%2,%3}, {%4,%5,%6,%7}, {%8,%9}, {%0,%1,%2,%3};"
        : "+f"(c[0]), "+f"(c[1]), "+f"(c[2]), "+f"(c[3])
        : "r"(a.x), "r"(a.y), "r"(a.z), "r"(a.w), "r"(b0), "r"(b1));
}

// =====================================================================
// K2: tf32 mma.sync fused scores.
// C[32768,2048] = enc @ WaE^T ; spart[m,nt] = sum_n w2[n]*tanh(C+hproj)
// CTA 128x256x32, 8 warps (2x4) of 64x64, m16n8k8, double-buffered smem
// in fragment-major swizzled layout (all consumer loads = LDS.128).
// grid (8 n-tiles, 256 m-tiles), 256 threads.
// =====================================================================
#define A_FLOATS     4096            // 128x32
#define B_FLOATS     8192            // 256x32
#define STAGE_FLOATS (A_FLOATS + B_FLOATS)
#define SMEM_FLOATS  (2 * STAGE_FLOATS)          // 24576 floats = 96KB
#define SMEM_BYTES   (SMEM_FLOATS * 4)

__device__ __forceinline__ void stsA(float* st, int amt, int arr, int aq, const float4* aR) {
#pragma unroll
    for (int i = 0; i < 4; i++) {
        const int q = aq + i;
        const int ks = q >> 1;
        const int regb = (arr >> 3) | ((q & 1) << 1);
        const float v[4] = {aR[i].x, aR[i].y, aR[i].z, aR[i].w};
#pragma unroll
        for (int j = 0; j < 4; j++) {
            const int swz = ((arr & 1) << 1) | (j >> 1);
            const int off = amt * 512 + (((arr & 7) << 2) | j) * 16
                          + ((ks ^ swz) << 2) + regb;
            st[off] = tf32r(v[j]);
        }
    }
}
__device__ __forceinline__ void stsB(float* st, int bng, int bnn, const float4* bR) {
#pragma unroll
    for (int q = 0; q < 8; q++) {
        const float v[4] = {bR[q].x, bR[q].y, bR[q].z, bR[q].w};
        const int base = bng * 256 + (bnn << 2) * 8
                       + (((q >> 2) ^ (bnn & 1)) << 2)
                       + (((q >> 1) & 1) << 1) + (q & 1);
#pragma unroll
        for (int j = 0; j < 4; j++) st[base + j * 8] = tf32r(v[j]);
    }
}

__global__ __launch_bounds__(256, 1)
void fused_scores_tc(const float* __restrict__ enc,
                     const float* __restrict__ Wa,
                     const float* __restrict__ w2)
{
    extern __shared__ __align__(16) float sm[];
    const int tid  = threadIdx.x;
    const int lane = tid & 31;
    const int wid  = tid >> 5;
    const int wm   = wid >> 2;    // 0..1
    const int wn   = wid & 3;     // 0..3
    const int n0 = blockIdx.x * 256;
    const int m0 = blockIdx.y * 128;

    // staging indices
    const int ar  = tid >> 1;          // A row 0..127
    const int aq  = (tid & 1) * 4;     // first of 4 float4 cols
    const int amt = ar >> 4;
    const int arr = ar & 15;
    const int bnn = tid & 7;
    const int bng = tid >> 3;

    const float* gA = enc + (size_t)(m0 + ar) * 1024;
    const float* gB = Wa  + (size_t)(n0 + tid) * 2048 + 1024;

    const int swA = (lane >> 1) & 3;
    const int swB = (lane >> 2) & 1;

    float acc[4][8][4];
#pragma unroll
    for (int i = 0; i < 4; i++)
#pragma unroll
        for (int j = 0; j < 8; j++)
#pragma unroll
            for (int r = 0; r < 4; r++) acc[i][j][r] = 0.f;

    float4 aR[4], bR[8];
    // prologue: chunk 0
#pragma unroll
    for (int i = 0; i < 4; i++) aR[i] = *(const float4*)(gA + (aq + i) * 4);
#pragma unroll
    for (int q = 0; q < 8; q++) bR[q] = *(const float4*)(gB + q * 4);
    stsA(sm, amt, arr, aq, aR);
    stsB(sm + A_FLOATS, bng, bnn, bR);
    __syncthreads();

#pragma unroll 1
    for (int ch = 0; ch < 32; ch++) {
        if (ch < 31) {
            const float* pA = gA + (ch + 1) * 32;
            const float* pB = gB + (ch + 1) * 32;
#pragma unroll
            for (int i = 0; i < 4; i++) aR[i] = *(const float4*)(pA + (aq + i) * 4);
#pragma unroll
            for (int q = 0; q < 8; q++) bR[q] = *(const float4*)(pB + q * 4);
        }
        const float* sA = sm + (ch & 1) * STAGE_FLOATS;
        const float* sB = sA + A_FLOATS;
#pragma unroll
        for (int kp = 0; kp < 2; kp++) {
            uint4 bq[8];
#pragma unroll
            for (int nt = 0; nt < 8; nt++)
                bq[nt] = *(const uint4*)(sB + (wn * 8 + nt) * 256 + lane * 8 + ((kp ^ swB) << 2));
#pragma unroll
            for (int h = 0; h < 2; h++) {
                const int ks = kp * 2 + h;
                uint4 aq4[4];
#pragma unroll
                for (int i = 0; i < 4; i++)
                    aq4[i] = *(const uint4*)(sA + (wm * 4 + i) * 512 + lane * 16 + ((ks ^ swA) << 2));
#pragma unroll
                for (int i = 0; i < 4; i++)
#pragma unroll
                    for (int nt = 0; nt < 8; nt++) {
                        const unsigned b0 = h ? bq[nt].z : bq[nt].x;
                        const unsigned b1 = h ? bq[nt].w : bq[nt].y;
                        mma_tf32(acc[i][nt], aq4[i], b0, b1);
                    }
            }
        }
        if (ch < 31) {
            float* nst = sm + ((ch + 1) & 1) * STAGE_FLOATS;
            stsA(nst, amt, arr, aq, aR);
            stsB(nst + A_FLOATS, bng, bnn, bR);
            __syncthreads();
        }
    }

    __syncthreads();   // protect smem reuse against last-chunk readers

    // stage hproj [64 x 256] (stride 260) + w2 + red buffer
    float* hp_s = sm;
    float* w2_s = sm + 64 * 260;          // 16640
    float* red  = w2_s + 256;             // 16896 .. 17408
    for (int i = tid; i < 64 * 256; i += 256) {
        const int b = i >> 8, c = i & 255;
        hp_s[b * 260 + c] = g_hproj[(size_t)b * 2048 + n0 + c];
    }
    w2_s[tid] = w2[n0 + tid];
    __syncthreads();

    const int g  = lane >> 2;
    const int cb = (lane & 3) * 2;
#pragma unroll
    for (int mt = 0; mt < 4; mt++) {
        const int r1 = mt * 16 + g;
        const int r2 = r1 + 8;
        float s1 = 0.f, s2 = 0.f;
#pragma unroll
        for (int nt = 0; nt < 8; nt++) {
            const int col = wn * 64 + nt * 8 + cb;
            const float w0 = w2_s[col], w1 = w2_s[col + 1];
            const float h10 = hp_s[r1 * 260 + col], h11 = hp_s[r1 * 260 + col + 1];
            const float h20 = hp_s[r2 * 260 + col], h21 = hp_s[r2 * 260 + col + 1];
            s1 = fmaf(fast_tanh(acc[mt][nt][0] + h10), w0, s1);
            s1 = fmaf(fast_tanh(acc[mt][nt][1] + h11), w1, s1);
            s2 = fmaf(fast_tanh(acc[mt][nt][2] + h20), w0, s2);
            s2 = fmaf(fast_tanh(acc[mt][nt][3] + h21), w1, s2);
        }
        s1 += __shfl_down_sync(0xffffffffu, s1, 2, 4);
        s1 += __shfl_down_sync(0xffffffffu, s1, 1, 4);
        s2 += __shfl_down_sync(0xffffffffu, s2, 2, 4);
        s2 += __shfl_down_sync(0xffffffffu, s2, 1, 4);
        if ((lane & 3) == 0) {
            red[(wm * 64 + r1) * 4 + wn] = s1;
            red[(wm * 64 + r2) * 4 + wn] = s2;
        }
    }
    __syncthreads();
    if (tid < 128) {
        const float v = red[tid * 4] + red[tid * 4 + 1] + red[tid * 4 + 2] + red[tid * 4 + 3];
        g_spart[(size_t)(m0 + tid) * NTILES + blockIdx.x] = v;
    }
}

// =====================================================================
// Small generic GEMM (K1, K6): C = epi([A|A2] @ B^T + bias)
// =====================================================================
__global__ void small_gemm_kernel(const float* __restrict__ A,
                                  const float* __restrict__ A2, int ksplit, int lda,
                                  const float* __restrict__ Bm, int ldb,
                                  const float* __restrict__ bias,
                                  float* __restrict__ Cout, int ldc,
                                  int M, int N, int K, int do_tanh)
{
    __shared__ float As[16][33];
    __shared__ float Bs[16][33];
    float* C = Cout ? Cout : g_hproj;
    const int tid = threadIdx.x;
    const int tx = tid & 15, ty = tid >> 4;
    const int m0 = blockIdx.y * 32, n0 = blockIdx.x * 32;
    float acc00 = 0.f, acc01 = 0.f, acc10 = 0.f, acc11 = 0.f;

    for (int k0 = 0; k0 < K; k0 += 16) {
        for (int i = tid; i < 32 * 16; i += 256) {
            const int r = i >> 4, c = i & 15;
            const int m = m0 + r, k = k0 + c;
            float av = 0.f;
            if (m < M) av = (k < ksplit) ? A[(size_t)m * lda + k]
                                         : A2[(size_t)m * lda + (k - ksplit)];
            As[c][r] = av;
            const int n = n0 + r;
            Bs[c][r] = (n < N) ? Bm[(size_t)n * ldb + k] : 0.f;
        }
        __syncthreads();
#pragma unroll
        for (int k = 0; k < 16; k++) {
            const float a0 = As[k][ty * 2], a1 = As[k][ty * 2 + 1];
            const float b0 = Bs[k][tx * 2], b1 = Bs[k][tx * 2 + 1];
            acc00 = fmaf(a0, b0, acc00); acc01 = fmaf(a0, b1, acc01);
            acc10 = fmaf(a1, b0, acc10); acc11 = fmaf(a1, b1, acc11);
        }
        __syncthreads();
    }
    const float r2[2][2] = {{acc00, acc01}, {acc10, acc11}};
#pragma unroll
    for (int i = 0; i < 2; i++)
#pragma unroll
        for (int j = 0; j < 2; j++) {
            const int mm = m0 + ty * 2 + i, nn = n0 + tx * 2 + j;
            if (mm < M && nn < N) {
                float v = r2[i][j] + bias[nn];
                if (do_tanh) v = fast_tanh(v);
                C[(size_t)mm * ldc + nn] = v;
            }
        }
}

// =====================================================================
// K3: reduce partial scores + softmax
// =====================================================================
__global__ void softmax_kernel(const float* __restrict__ b2)
{
    const int b = blockIdx.x;
    const int tid = threadIdx.x;
    __shared__ float red[256];
    const float b2v = b2[0];

    float loc[2];
#pragma unroll
    for (int s = 0; s < 2; s++) {
        const int t = tid + s * 256;
        const float* p = g_spart + (size_t)(t * NB + b) * NTILES;
        float a = b2v;
#pragma unroll
        for (int n = 0; n < NTILES; n++) a += p[n];
        loc[s] = a;
    }
    red[tid] = fmaxf(loc[0], loc[1]);
    __syncthreads();
    for (int off = 128; off > 0; off >>= 1) {
        if (tid < off) red[tid] = fmaxf(red[tid], red[tid + off]);
        __syncthreads();
    }
    const float mx = red[0];
    __syncthreads();
    const float e0 = expf(loc[0] - mx);
    const float e1 = expf(loc[1] - mx);
    red[tid] = e0 + e1;
    __syncthreads();
    for (int off = 128; off > 0; off >>= 1) {
        if (tid < off) red[tid] += red[tid + off];
        __syncthreads();
    }
    const float inv = 1.f / red[0];
    g_weights[b * NTT + tid]       = e0 * inv;
    g_weights[b * NTT + tid + 256] = e1 * inv;
}

// =====================================================================
// K4: applied partials over 4 T-chunks, then reduce
// =====================================================================
__global__ void applied_part_kernel(const float* __restrict__ enc)
{
    const int b  = blockIdx.y;
    const int e  = blockIdx.x * 256 + threadIdx.x;
    const int t0 = blockIdx.z * 128;
    __shared__ float w[128];
    if (threadIdx.x < 128) w[threadIdx.x] = g_weights[b * NTT + t0 + threadIdx.x];
    __syncthreads();
    const float* p = enc + ((size_t)t0 * NB + b) * 1024 + e;
    float acc = 0.f;
#pragma unroll 8
    for (int t = 0; t < 128; t++)
        acc = fmaf(w[t], p[(size_t)t * (NB * NE)], acc);
    g_apart[blockIdx.z][b * 1024 + e] = acc;
}

__global__ void applied_reduce_kernel(float* __restrict__ applied)
{
    const int i = blockIdx.x * 256 + threadIdx.x;
    applied[i] = g_apart[0][i] + g_apart[1][i] + g_apart[2][i] + g_apart[3][i];
}

// =====================================================================
extern "C" void kernel_launch(void* const* d_in, const int* in_sizes, int n_in,
                              void* d_out, int out_size)
{
    const float* hidden = (const float*)d_in[0];
    const float* dec    = (const float*)d_in[1];
    const float* enc    = (const float*)d_in[2];
    const float* Wa     = (const float*)d_in[3];
    const float* ba     = (const float*)d_in[4];
    const float* w2     = (const float*)d_in[5];
    const float* b2     = (const float*)d_in[6];
    const float* Wc     = (const float*)d_in[7];
    const float* bc     = (const float*)d_in[8];

    float* out     = (float*)d_out;
    float* applied = out + NB * ND;

    cudaFuncSetAttribute(fused_scores_tc,
                         cudaFuncAttributeMaxDynamicSharedMemorySize, SMEM_BYTES);

    // K1: h_proj = hidden @ Wa[:, :1024]^T + ba  -> g_hproj
    small_gemm_kernel<<<dim3(NF / 32, NB / 32), 256>>>(
        hidden, hidden, 1024, 1024, Wa, 2048, ba,
        nullptr, NF, NB, NF, 1024, 0);

    // K2: tf32 tensor-core fused scores -> g_spart
    fused_scores_tc<<<dim3(NTILES, NM / 128), 256, SMEM_BYTES>>>(enc, Wa, w2);

    // K3: softmax -> g_weights
    softmax_kernel<<<NB, 256>>>(b2);

    // K4: applied partials + reduce -> d_out second half
    applied_part_kernel<<<dim3(NE / 256, NB, 4), 256>>>(enc);
    applied_reduce_kernel<<<(NB * NE) / 256, 256>>>(applied);

    // K5: out = tanh([dec|applied] @ Wc^T + bc) -> d_out first half
    small_gemm_kernel<<<dim3(ND / 32, NB / 32), 256>>>(
        dec, applied, 1024, 1024, Wc, 2048, bc,
        out, ND, NB, ND, 2048, 1);
}